// round 1
// baseline (speedup 1.0000x reference)
#include <cuda_runtime.h>

#define NPROP   2048
#define MAXN    256
#define D1      64
#define D2      128
#define D3      256
#define MIN_PTS 4
#define EPS     1e-6f

// Shared-memory layout (in floats)
#define H2ROW   132                       // 128 + 4 pad: 16B-aligned rows, conflict-spread
#define OFF_W1  0                         // 3*64   = 192
#define OFF_B1  192                       // 64
#define OFF_W2  256                       // 64*128 = 8192
#define OFF_B2  8448                      // 128
#define OFF_B3  8576                      // 256
#define OFF_FE  8832                      // 256 (pooled feats)
#define OFF_H2  9088                      // 256*132 = 33792
#define SMEM_FLOATS (OFF_H2 + MAXN * H2ROW)
#define SMEM_BYTES  (SMEM_FLOATS * 4)     // 171,520 B

__global__ __launch_bounds__(256, 1)
void refine_head_kernel(const float* __restrict__ points,
                        const int*   __restrict__ counts,
                        const float* __restrict__ proposals,
                        const float* __restrict__ W1, const float* __restrict__ b1,
                        const float* __restrict__ W2, const float* __restrict__ b2,
                        const float* __restrict__ W3, const float* __restrict__ b3,
                        const float* __restrict__ Wc, const float* __restrict__ bc,
                        const float* __restrict__ Wr, const float* __restrict__ br,
                        float* __restrict__ out)
{
    extern __shared__ float sm[];
    const int b   = blockIdx.x;
    const int tid = threadIdx.x;
    const int n   = counts[b];

    // Invalid proposal: feats = 0 -> outputs are pure biases. No sync before this
    // early-out (uniform per block), so it's safe.
    if (n < MIN_PTS) {
        if (tid == 0) out[b] = bc[0];
        if (tid < 6)  out[NPROP + b * 6 + tid] = br[tid];
        return;
    }

    // ---- Stage weights into smem ----
    for (int i = tid; i < 192; i += 256)  sm[OFF_W1 + i] = W1[i];
    if (tid < 64)                         sm[OFF_B1 + tid] = b1[tid];
    for (int i = tid; i < 8192; i += 256) sm[OFF_W2 + i] = W2[i];
    if (tid < 128)                        sm[OFF_B2 + tid] = b2[tid];
    sm[OFF_B3 + tid] = b3[tid];
    __syncthreads();

    // ---- Phase A: thread = point index (only first n unique points matter;
    // the reference's arange(256) % n gather only duplicates them, and max-pool
    // is duplicate-invariant). Compute h2[point][128] into smem. ----
    if (tid < n) {
        const float* pp = points + ((long)b * MAXN + tid) * 3;
        const float* pr = proposals + b * 6;
        const float c0 = (pp[0] - pr[0]) / (fabsf(pr[3]) + EPS);
        const float c1 = (pp[1] - pr[1]) / (fabsf(pr[4]) + EPS);
        const float c2 = (pp[2] - pr[2]) / (fabsf(pr[5]) + EPS);

        float h1[D1];
        {
            const float4* r0 = (const float4*)&sm[OFF_W1 + 0];
            const float4* r1 = (const float4*)&sm[OFF_W1 + 64];
            const float4* r2 = (const float4*)&sm[OFF_W1 + 128];
            const float4* bb = (const float4*)&sm[OFF_B1];
            #pragma unroll
            for (int q = 0; q < 16; q++) {
                float4 a = r0[q], d = r1[q], e = r2[q], f = bb[q];
                h1[q*4+0] = fmaxf(fmaf(c0, a.x, fmaf(c1, d.x, fmaf(c2, e.x, f.x))), 0.f);
                h1[q*4+1] = fmaxf(fmaf(c0, a.y, fmaf(c1, d.y, fmaf(c2, e.y, f.y))), 0.f);
                h1[q*4+2] = fmaxf(fmaf(c0, a.z, fmaf(c1, d.z, fmaf(c2, e.z, f.z))), 0.f);
                h1[q*4+3] = fmaxf(fmaf(c0, a.w, fmaf(c1, d.w, fmaf(c2, e.w, f.w))), 0.f);
            }
        }

        // h2 in 4 chunks of 32 channels to bound register pressure
        #pragma unroll
        for (int cc = 0; cc < 4; cc++) {
            float acc[32];
            {
                const float4* bb = (const float4*)&sm[OFF_B2 + cc * 32];
                #pragma unroll
                for (int q = 0; q < 8; q++) {
                    float4 v = bb[q];
                    acc[q*4+0] = v.x; acc[q*4+1] = v.y; acc[q*4+2] = v.z; acc[q*4+3] = v.w;
                }
            }
            #pragma unroll 8
            for (int i = 0; i < D1; i++) {
                const float hv = h1[i];
                const float4* wr = (const float4*)&sm[OFF_W2 + i * D2 + cc * 32];
                #pragma unroll
                for (int q = 0; q < 8; q++) {
                    float4 w = wr[q];
                    acc[q*4+0] = fmaf(hv, w.x, acc[q*4+0]);
                    acc[q*4+1] = fmaf(hv, w.y, acc[q*4+1]);
                    acc[q*4+2] = fmaf(hv, w.z, acc[q*4+2]);
                    acc[q*4+3] = fmaf(hv, w.w, acc[q*4+3]);
                }
            }
            float4* dst = (float4*)&sm[OFF_H2 + tid * H2ROW + cc * 32];
            #pragma unroll
            for (int q = 0; q < 8; q++) {
                dst[q] = make_float4(fmaxf(acc[q*4+0], 0.f), fmaxf(acc[q*4+1], 0.f),
                                     fmaxf(acc[q*4+2], 0.f), fmaxf(acc[q*4+3], 0.f));
            }
        }
    }
    __syncthreads();

    // ---- Phase B: thread = output channel k. W3 column in registers (L2-hot,
    // coalesced); h2 rows broadcast-read from smem; running max over points. ----
    {
        const int k = tid;
        float w3c[D2];
        #pragma unroll
        for (int j = 0; j < D2; j++) w3c[j] = W3[j * D3 + k];

        float m = -3.402823466e38f;
        for (int p = 0; p < n; p++) {
            const float4* row = (const float4*)&sm[OFF_H2 + p * H2ROW];
            float a0 = 0.f, a1 = 0.f, a2 = 0.f, a3 = 0.f;
            #pragma unroll
            for (int q = 0; q < 32; q++) {
                float4 hv = row[q];
                a0 = fmaf(hv.x, w3c[q*4+0], a0);
                a1 = fmaf(hv.y, w3c[q*4+1], a1);
                a2 = fmaf(hv.z, w3c[q*4+2], a2);
                a3 = fmaf(hv.w, w3c[q*4+3], a3);
            }
            m = fmaxf(m, (a0 + a1) + (a2 + a3));
        }
        sm[OFF_FE + k] = m + sm[OFF_B3 + k];
    }
    __syncthreads();

    // ---- Heads: 7 warps, each one dot(feats, column) + bias ----
    {
        const int w = tid >> 5, lane = tid & 31;
        if (w < 7) {
            float s = 0.f;
            if (w == 0) {
                #pragma unroll
                for (int k = lane; k < D3; k += 32) s += sm[OFF_FE + k] * Wc[k];
            } else {
                const int r = w - 1;
                #pragma unroll
                for (int k = lane; k < D3; k += 32) s += sm[OFF_FE + k] * Wr[k * 6 + r];
            }
            #pragma unroll
            for (int off = 16; off > 0; off >>= 1)
                s += __shfl_down_sync(0xffffffffu, s, off);
            if (lane == 0) {
                if (w == 0) out[b] = s + bc[0];
                else        out[NPROP + b * 6 + (w - 1)] = s + br[w - 1];
            }
        }
    }
}

extern "C" void kernel_launch(void* const* d_in, const int* in_sizes, int n_in,
                              void* d_out, int out_size)
{
    const float* points    = (const float*)d_in[0];
    const int*   counts    = (const int*)  d_in[1];
    const float* proposals = (const float*)d_in[2];
    const float* W1 = (const float*)d_in[3];
    const float* b1 = (const float*)d_in[4];
    const float* W2 = (const float*)d_in[5];
    const float* b2 = (const float*)d_in[6];
    const float* W3 = (const float*)d_in[7];
    const float* b3 = (const float*)d_in[8];
    const float* Wc = (const float*)d_in[9];
    const float* bc = (const float*)d_in[10];
    const float* Wr = (const float*)d_in[11];
    const float* br = (const float*)d_in[12];
    float* out = (float*)d_out;

    cudaFuncSetAttribute(refine_head_kernel,
                         cudaFuncAttributeMaxDynamicSharedMemorySize, SMEM_BYTES);
    refine_head_kernel<<<NPROP, 256, SMEM_BYTES>>>(
        points, counts, proposals, W1, b1, W2, b2, W3, b3, Wc, bc, Wr, br, out);
}

// round 2
// speedup vs baseline: 1.1420x; 1.1420x over previous
#include <cuda_runtime.h>
#include <cstdint>

#define NPROP   2048
#define MAXN    256
#define D1      64
#define D2      128
#define D3      256
#define MIN_PTS 4
#define EPS     1e-6f

// Shared-memory layout (in floats)
#define H2ROW   132                       // 128 + 4 pad
#define OFF_W1  0                         // 3*64   = 192
#define OFF_B1  192                       // 64
#define OFF_W2  256                       // 64*128 = 8192 (i-pair interleaved)
#define OFF_B2  8448                      // 128
#define OFF_B3  8576                      // 256
#define OFF_FE  8832                      // 256 (pooled feats)
#define OFF_H2  9088                      // 256*132 = 33792
#define SMEM_FLOATS (OFF_H2 + MAXN * H2ROW)
#define SMEM_BYTES  (SMEM_FLOATS * 4)     // 171,520 B

// Packed fp32x2 helpers (Blackwell packed-fp32; PTX-only, ptxas won't auto-fuse)
#define FMA2(d, a, b, c) \
    asm("fma.rn.f32x2 %0, %1, %2, %3;" : "=l"(d) : "l"(a), "l"(b), "l"(c))
#define PACKF2(d, lo, hi) \
    asm("mov.b64 %0, {%1, %2};" : "=l"(d) : "r"(__float_as_uint(lo)), "r"(__float_as_uint(hi)))
#define UNPACKF2(lo, hi, in) do { unsigned _l, _h;                              \
    asm("mov.b64 {%0, %1}, %2;" : "=r"(_l), "=r"(_h) : "l"(in));                \
    lo = __uint_as_float(_l); hi = __uint_as_float(_h); } while (0)

typedef unsigned long long u64;

__global__ __launch_bounds__(256, 1)
void refine_head_kernel(const float* __restrict__ points,
                        const int*   __restrict__ counts,
                        const float* __restrict__ proposals,
                        const float* __restrict__ W1, const float* __restrict__ b1,
                        const float* __restrict__ W2, const float* __restrict__ b2,
                        const float* __restrict__ W3, const float* __restrict__ b3,
                        const float* __restrict__ Wc, const float* __restrict__ bc,
                        const float* __restrict__ Wr, const float* __restrict__ br,
                        float* __restrict__ out)
{
    extern __shared__ float sm[];
    const int b   = blockIdx.x;
    const int tid = threadIdx.x;
    const int n   = counts[b];

    // Invalid proposal: feats = 0 -> outputs are pure biases (uniform early-out).
    if (n < MIN_PTS) {
        if (tid == 0) out[b] = bc[0];
        if (tid < 6)  out[NPROP + b * 6 + tid] = br[tid];
        return;
    }

    // ---- Stage weights into smem. W2 goes in i-pair interleaved:
    // smem pair layout: W2p[ip][k] = (W2[2ip][k], W2[2ip+1][k]) adjacent. ----
    for (int i = tid; i < 192; i += 256)  sm[OFF_W1 + i] = W1[i];
    if (tid < 64)                         sm[OFF_B1 + tid] = b1[tid];
    for (int idx = tid; idx < 8192; idx += 256) {
        int i = idx >> 7, k = idx & 127;
        sm[OFF_W2 + ((i >> 1) << 8) + (k << 1) + (i & 1)] = W2[idx];
    }
    if (tid < 128)                        sm[OFF_B2 + tid] = b2[tid];
    sm[OFF_B3 + tid] = b3[tid];
    __syncthreads();

    // ---- Phase A: thread = point (only first n unique points matter: the
    // reference gather arange(256)%n only duplicates points, and max-pool is
    // duplicate-invariant). h2[point][128] -> smem, fp32x2-packed over i. ----
    if (tid < n) {
        const float* pp = points + ((long)b * MAXN + tid) * 3;
        const float* pr = proposals + b * 6;
        const float c0 = (pp[0] - pr[0]) / (fabsf(pr[3]) + EPS);
        const float c1 = (pp[1] - pr[1]) / (fabsf(pr[4]) + EPS);
        const float c2 = (pp[2] - pr[2]) / (fabsf(pr[5]) + EPS);

        // h1 + relu, then pack into 32 b64 i-pairs
        u64 hp[32];
        {
            const float4* r0 = (const float4*)&sm[OFF_W1 + 0];
            const float4* r1 = (const float4*)&sm[OFF_W1 + 64];
            const float4* r2 = (const float4*)&sm[OFF_W1 + 128];
            const float4* bb = (const float4*)&sm[OFF_B1];
            #pragma unroll
            for (int q = 0; q < 16; q++) {
                float4 a = r0[q], d = r1[q], e = r2[q], f = bb[q];
                float h0 = fmaxf(fmaf(c0, a.x, fmaf(c1, d.x, fmaf(c2, e.x, f.x))), 0.f);
                float h1v= fmaxf(fmaf(c0, a.y, fmaf(c1, d.y, fmaf(c2, e.y, f.y))), 0.f);
                float h2v= fmaxf(fmaf(c0, a.z, fmaf(c1, d.z, fmaf(c2, e.z, f.z))), 0.f);
                float h3 = fmaxf(fmaf(c0, a.w, fmaf(c1, d.w, fmaf(c2, e.w, f.w))), 0.f);
                PACKF2(hp[q*2+0], h0, h1v);
                PACKF2(hp[q*2+1], h2v, h3);
            }
        }

        // h2 in 4 chunks of 32 channels; acc.lo = even-i partial, .hi = odd-i
        #pragma unroll
        for (int cc = 0; cc < 4; cc++) {
            u64 acc[32];
            #pragma unroll
            for (int c = 0; c < 32; c++) acc[c] = 0ull;

            #pragma unroll 8
            for (int ip = 0; ip < 32; ip++) {
                const ulonglong2* wrow =
                    (const ulonglong2*)&sm[OFF_W2 + ip * 256 + cc * 64];
                const u64 h = hp[ip];
                #pragma unroll
                for (int q = 0; q < 16; q++) {
                    ulonglong2 w = wrow[q];
                    FMA2(acc[q*2+0], h, w.x, acc[q*2+0]);
                    FMA2(acc[q*2+1], h, w.y, acc[q*2+1]);
                }
            }

            const float* b2c = &sm[OFF_B2 + cc * 32];
            float4* dst = (float4*)&sm[OFF_H2 + tid * H2ROW + cc * 32];
            #pragma unroll
            for (int q = 0; q < 8; q++) {
                float v[4];
                #pragma unroll
                for (int t = 0; t < 4; t++) {
                    float lo, hi; UNPACKF2(lo, hi, acc[q*4+t]);
                    v[t] = fmaxf(lo + hi + b2c[q*4+t], 0.f);
                }
                dst[q] = make_float4(v[0], v[1], v[2], v[3]);
            }
        }
    }
    __syncthreads();

    // ---- Phase B: thread = output channel k. W3 column packed into 64 b64
    // j-pairs in regs; h2 rows broadcast from smem as b64 pairs. ----
    {
        const int k = tid;
        u64 w3p[64];
        #pragma unroll
        for (int q = 0; q < 64; q++) {
            float a = W3[(2*q    ) * D3 + k];
            float c = W3[(2*q + 1) * D3 + k];
            PACKF2(w3p[q], a, c);
        }

        float m = -3.402823466e38f;
        for (int p = 0; p < n; p++) {
            const ulonglong2* row = (const ulonglong2*)&sm[OFF_H2 + p * H2ROW];
            u64 a0 = 0ull, a1 = 0ull, a2 = 0ull, a3 = 0ull;
            #pragma unroll
            for (int q = 0; q < 16; q++) {
                ulonglong2 hv0 = row[2*q];
                ulonglong2 hv1 = row[2*q + 1];
                FMA2(a0, hv0.x, w3p[4*q + 0], a0);
                FMA2(a1, hv0.y, w3p[4*q + 1], a1);
                FMA2(a2, hv1.x, w3p[4*q + 2], a2);
                FMA2(a3, hv1.y, w3p[4*q + 3], a3);
            }
            float l0,h0,l1,h1,l2,h2,l3,h3;
            UNPACKF2(l0,h0,a0); UNPACKF2(l1,h1,a1);
            UNPACKF2(l2,h2,a2); UNPACKF2(l3,h3,a3);
            m = fmaxf(m, ((l0+h0)+(l1+h1)) + ((l2+h2)+(l3+h3)));
        }
        sm[OFF_FE + k] = m + sm[OFF_B3 + k];
    }
    __syncthreads();

    // ---- Heads: 7 warps, each one dot(feats, column) + bias ----
    {
        const int w = tid >> 5, lane = tid & 31;
        if (w < 7) {
            float s = 0.f;
            if (w == 0) {
                #pragma unroll
                for (int k = lane; k < D3; k += 32) s += sm[OFF_FE + k] * Wc[k];
            } else {
                const int r = w - 1;
                #pragma unroll
                for (int k = lane; k < D3; k += 32) s += sm[OFF_FE + k] * Wr[k * 6 + r];
            }
            #pragma unroll
            for (int off = 16; off > 0; off >>= 1)
                s += __shfl_down_sync(0xffffffffu, s, off);
            if (lane == 0) {
                if (w == 0) out[b] = s + bc[0];
                else        out[NPROP + b * 6 + (w - 1)] = s + br[w - 1];
            }
        }
    }
}

extern "C" void kernel_launch(void* const* d_in, const int* in_sizes, int n_in,
                              void* d_out, int out_size)
{
    const float* points    = (const float*)d_in[0];
    const int*   counts    = (const int*)  d_in[1];
    const float* proposals = (const float*)d_in[2];
    const float* W1 = (const float*)d_in[3];
    const float* b1 = (const float*)d_in[4];
    const float* W2 = (const float*)d_in[5];
    const float* b2 = (const float*)d_in[6];
    const float* W3 = (const float*)d_in[7];
    const float* b3 = (const float*)d_in[8];
    const float* Wc = (const float*)d_in[9];
    const float* bc = (const float*)d_in[10];
    const float* Wr = (const float*)d_in[11];
    const float* br = (const float*)d_in[12];
    float* out = (float*)d_out;

    cudaFuncSetAttribute(refine_head_kernel,
                         cudaFuncAttributeMaxDynamicSharedMemorySize, SMEM_BYTES);
    refine_head_kernel<<<NPROP, 256, SMEM_BYTES>>>(
        points, counts, proposals, W1, b1, W2, b2, W3, b3, Wc, bc, Wr, br, out);
}

// round 9
// speedup vs baseline: 2.2848x; 2.0006x over previous
#include <cuda_runtime.h>
#include <cstdint>

#define NPROP   2048
#define MAXN    256
#define D1      64
#define D2      128
#define D3      256
#define MIN_PTS 4
#define EPS     1e-6f

// ---- smem layout (float offsets) ----
#define OFF_W1   0        // 192 (phase A only; FE overwrites later)
#define OFF_B1   192      // 64
#define OFF_FE   0        // 256 pooled feats (after phase A)
#define OFF_W2   256      // 8192, i-pair interleaved
#define OFF_B2   8448     // 128
#define OFF_B3   8576     // 256
#define H2TROW   264      // 256 + 8 pad -> conflict-free col writes & B-frag reads
#define OFF_H2T  9088     // h2 transposed [j=128][pt=256] (33792 floats)
#define SMEM_FLOATS (OFF_H2T + D2 * H2TROW)   // 42880
#define SMEM_BYTES  (SMEM_FLOATS * 4)         // 171,520 B (validated in R1/R2)

typedef unsigned long long u64;

// ---- packed fp32x2 (phase A) ----
#define FMA2(d, a, b, c) \
    asm("fma.rn.f32x2 %0, %1, %2, %3;" : "=l"(d) : "l"(a), "l"(b), "l"(c))
#define PACKF2(d, lo, hi) \
    asm("mov.b64 %0, {%1, %2};" : "=l"(d) : "r"(__float_as_uint(lo)), "r"(__float_as_uint(hi)))
#define UNPACKF2(lo, hi, in) do { unsigned _l, _h;                              \
    asm("mov.b64 {%0, %1}, %2;" : "=r"(_l), "=r"(_h) : "l"(in));                \
    lo = __uint_as_float(_l); hi = __uint_as_float(_h); } while (0)

// round fp32 -> nearest tf32-representable value (bits)
__device__ __forceinline__ uint32_t f32_to_tf32_bits(float x) {
    uint32_t r;
    asm("cvt.rna.tf32.f32 %0, %1;" : "=r"(r) : "f"(x));
    return r;
}

// Standard PTX tensor-core MMA (sm_80+ feature set; compiles under compute_103):
// D(16x8) += A(16x8,row) * B(8x8,col), tf32 in, f32 accum.
#define MMA_TF32(c, a, b) \
    asm volatile("mma.sync.aligned.m16n8k8.row.col.f32.tf32.tf32.f32 " \
        "{%0,%1,%2,%3}, {%4,%5,%6,%7}, {%8,%9}, {%0,%1,%2,%3};" \
        : "+f"((c)[0]), "+f"((c)[1]), "+f"((c)[2]), "+f"((c)[3]) \
        : "r"((a)[0]), "r"((a)[1]), "r"((a)[2]), "r"((a)[3]), \
          "r"((b)[0]), "r"((b)[1]))

__global__ __launch_bounds__(256, 1)
void refine_head_kernel(const float* __restrict__ points,
                        const int*   __restrict__ counts,
                        const float* __restrict__ proposals,
                        const float* __restrict__ W1, const float* __restrict__ b1,
                        const float* __restrict__ W2, const float* __restrict__ b2,
                        const float* __restrict__ W3, const float* __restrict__ b3,
                        const float* __restrict__ Wc, const float* __restrict__ bc,
                        const float* __restrict__ Wr, const float* __restrict__ br,
                        float* __restrict__ out)
{
    extern __shared__ float sm[];
    const int b    = blockIdx.x;
    const int tid  = threadIdx.x;
    const int wid  = tid >> 5;
    const int lane = tid & 31;
    const int n    = counts[b];

    // Invalid proposal: outputs are pure biases (uniform early-out).
    if (n < MIN_PTS) {
        if (tid == 0) out[b] = bc[0];
        if (tid < 6)  out[NPROP + b * 6 + tid] = br[tid];
        return;
    }

    // ---- Stage weights. W2 i-pair interleaved: (W2[2ip][k], W2[2ip+1][k]) adjacent. ----
    for (int i = tid; i < 192; i += 256)  sm[OFF_W1 + i] = W1[i];
    if (tid < 64)                         sm[OFF_B1 + tid] = b1[tid];
    for (int idx = tid; idx < 8192; idx += 256) {
        int i = idx >> 7, k = idx & 127;
        sm[OFF_W2 + ((i >> 1) << 8) + (k << 1) + (i & 1)] = W2[idx];
    }
    if (tid < 128)                        sm[OFF_B2 + tid] = b2[tid];
    sm[OFF_B3 + tid] = b3[tid];
    __syncthreads();

    // ---- Phase A: thread = point. Only the first n unique points matter (the
    // reference's arange(256)%n gather only duplicates points; max-pool is
    // duplicate-invariant). h2 -> h2t[j][pt] transposed, tf32-rounded. ----
    if (tid < n) {
        const float* pp = points + ((long)b * MAXN + tid) * 3;
        const float* pr = proposals + b * 6;
        const float c0 = (pp[0] - pr[0]) / (fabsf(pr[3]) + EPS);
        const float c1 = (pp[1] - pr[1]) / (fabsf(pr[4]) + EPS);
        const float c2 = (pp[2] - pr[2]) / (fabsf(pr[5]) + EPS);

        u64 hp[32];
        {
            const float4* r0 = (const float4*)&sm[OFF_W1 + 0];
            const float4* r1 = (const float4*)&sm[OFF_W1 + 64];
            const float4* r2 = (const float4*)&sm[OFF_W1 + 128];
            const float4* bb = (const float4*)&sm[OFF_B1];
            #pragma unroll
            for (int q = 0; q < 16; q++) {
                float4 a = r0[q], d = r1[q], e = r2[q], f = bb[q];
                float h0 = fmaxf(fmaf(c0, a.x, fmaf(c1, d.x, fmaf(c2, e.x, f.x))), 0.f);
                float h1v= fmaxf(fmaf(c0, a.y, fmaf(c1, d.y, fmaf(c2, e.y, f.y))), 0.f);
                float h2v= fmaxf(fmaf(c0, a.z, fmaf(c1, d.z, fmaf(c2, e.z, f.z))), 0.f);
                float h3 = fmaxf(fmaf(c0, a.w, fmaf(c1, d.w, fmaf(c2, e.w, f.w))), 0.f);
                PACKF2(hp[q*2+0], h0, h1v);
                PACKF2(hp[q*2+1], h2v, h3);
            }
        }

        #pragma unroll
        for (int cc = 0; cc < 4; cc++) {
            u64 acc[32];
            #pragma unroll
            for (int c = 0; c < 32; c++) acc[c] = 0ull;
            #pragma unroll 8
            for (int ip = 0; ip < 32; ip++) {
                const ulonglong2* wrow = (const ulonglong2*)&sm[OFF_W2 + ip * 256 + cc * 64];
                const u64 h = hp[ip];
                #pragma unroll
                for (int q = 0; q < 16; q++) {
                    ulonglong2 w = wrow[q];
                    FMA2(acc[q*2+0], h, w.x, acc[q*2+0]);
                    FMA2(acc[q*2+1], h, w.y, acc[q*2+1]);
                }
            }
            const float* b2c = &sm[OFF_B2 + cc * 32];
            #pragma unroll
            for (int q = 0; q < 8; q++) {
                #pragma unroll
                for (int t = 0; t < 4; t++) {
                    float lo, hi; UNPACKF2(lo, hi, acc[q*4+t]);
                    float v = fmaxf(lo + hi + b2c[q*4+t], 0.f);
                    const int j = cc * 32 + q * 4 + t;
                    sm[OFF_H2T + j * H2TROW + tid] =
                        __uint_as_float(f32_to_tf32_bits(v));
                }
            }
        }
    }
    __syncthreads();

    // ---- Phase B: layer-3 GEMM + max-pool on tensor cores (mma.sync tf32).
    // Warp w owns channels [w*32, w*32+32): 2 m16-tiles. A = W3T in registers
    // (loaded once, reused across all point chunks); B = h2t from smem. ----
    {
        const int tid4 = lane & 3;
        const int gid  = lane >> 2;
        const int chb  = wid * 32;

        // A fragments: A[s][mt][4], s = k-step (j = 8s + ...), mt = m16 tile.
        uint32_t A[16][2][4];
        #pragma unroll
        for (int s = 0; s < 16; s++) {
            const int j0 = s * 8 + tid4;
            #pragma unroll
            for (int mt = 0; mt < 2; mt++) {
                const int ch = chb + mt * 16 + gid;
                A[s][mt][0] = f32_to_tf32_bits(W3[j0 * D3 + ch]);
                A[s][mt][1] = f32_to_tf32_bits(W3[j0 * D3 + ch + 8]);
                A[s][mt][2] = f32_to_tf32_bits(W3[(j0 + 4) * D3 + ch]);
                A[s][mt][3] = f32_to_tf32_bits(W3[(j0 + 4) * D3 + ch + 8]);
            }
        }

        float mx[4] = {-3.402823466e38f, -3.402823466e38f,
                       -3.402823466e38f, -3.402823466e38f};   // [mt*2 + rowhalf]

        const int nchunks = (n + 15) >> 4;
        for (int ck = 0; ck < nchunks; ck++) {
            const int colb = ck * 16;
            float c[2][2][4];
            #pragma unroll
            for (int mt = 0; mt < 2; mt++)
                #pragma unroll
                for (int nt = 0; nt < 2; nt++)
                    #pragma unroll
                    for (int q = 0; q < 4; q++) c[mt][nt][q] = 0.f;

            #pragma unroll
            for (int s = 0; s < 16; s++) {
                uint32_t bf[2][2];
                #pragma unroll
                for (int nt = 0; nt < 2; nt++) {
                    const int col = colb + nt * 8 + gid;
                    bf[nt][0] = __float_as_uint(
                        sm[OFF_H2T + (s * 8 + tid4) * H2TROW + col]);
                    bf[nt][1] = __float_as_uint(
                        sm[OFF_H2T + (s * 8 + tid4 + 4) * H2TROW + col]);
                }
                #pragma unroll
                for (int mt = 0; mt < 2; mt++)
                    #pragma unroll
                    for (int nt = 0; nt < 2; nt++)
                        MMA_TF32(c[mt][nt], A[s][mt], bf[nt]);
            }

            // fold this chunk's D into running per-row max (mask cols >= n)
            #pragma unroll
            for (int mt = 0; mt < 2; mt++) {
                #pragma unroll
                for (int nt = 0; nt < 2; nt++) {
                    const int col0 = colb + nt * 8 + 2 * tid4;
                    if (col0 < n) {
                        mx[mt*2+0] = fmaxf(mx[mt*2+0], c[mt][nt][0]);
                        mx[mt*2+1] = fmaxf(mx[mt*2+1], c[mt][nt][2]);
                    }
                    if (col0 + 1 < n) {
                        mx[mt*2+0] = fmaxf(mx[mt*2+0], c[mt][nt][1]);
                        mx[mt*2+1] = fmaxf(mx[mt*2+1], c[mt][nt][3]);
                    }
                }
            }
        }

        // cross-lane max over the 4 lanes of each quad (they cover the 16 cols)
        #pragma unroll
        for (int o = 1; o < 4; o <<= 1) {
            #pragma unroll
            for (int q = 0; q < 4; q++)
                mx[q] = fmaxf(mx[q], __shfl_xor_sync(0xffffffffu, mx[q], o));
        }
        if (tid4 == 0) {
            #pragma unroll
            for (int mt = 0; mt < 2; mt++)
                #pragma unroll
                for (int rh = 0; rh < 2; rh++) {
                    const int ch = chb + mt * 16 + rh * 8 + gid;
                    sm[OFF_FE + ch] = mx[mt*2+rh] + sm[OFF_B3 + ch];
                }
        }
    }
    __syncthreads();

    // ---- Heads: 7 warps, each one dot(feats, column) + bias ----
    {
        if (wid < 7) {
            float s = 0.f;
            if (wid == 0) {
                #pragma unroll
                for (int k = lane; k < D3; k += 32) s += sm[OFF_FE + k] * Wc[k];
            } else {
                const int r = wid - 1;
                #pragma unroll
                for (int k = lane; k < D3; k += 32) s += sm[OFF_FE + k] * Wr[k * 6 + r];
            }
            #pragma unroll
            for (int off = 16; off > 0; off >>= 1)
                s += __shfl_down_sync(0xffffffffu, s, off);
            if (lane == 0) {
                if (wid == 0) out[b] = s + bc[0];
                else          out[NPROP + b * 6 + (wid - 1)] = s + br[wid - 1];
            }
        }
    }
}

extern "C" void kernel_launch(void* const* d_in, const int* in_sizes, int n_in,
                              void* d_out, int out_size)
{
    const float* points    = (const float*)d_in[0];
    const int*   counts    = (const int*)  d_in[1];
    const float* proposals = (const float*)d_in[2];
    const float* W1 = (const float*)d_in[3];
    const float* b1 = (const float*)d_in[4];
    const float* W2 = (const float*)d_in[5];
    const float* b2 = (const float*)d_in[6];
    const float* W3 = (const float*)d_in[7];
    const float* b3 = (const float*)d_in[8];
    const float* Wc = (const float*)d_in[9];
    const float* bc = (const float*)d_in[10];
    const float* Wr = (const float*)d_in[11];
    const float* br = (const float*)d_in[12];
    float* out = (float*)d_out;

    cudaFuncSetAttribute(refine_head_kernel,
                         cudaFuncAttributeMaxDynamicSharedMemorySize, SMEM_BYTES);
    refine_head_kernel<<<NPROP, 256, SMEM_BYTES>>>(
        points, counts, proposals, W1, b1, W2, b2, W3, b3, Wc, bc, Wr, br, out);
}

// round 10
// speedup vs baseline: 4.4914x; 1.9658x over previous
#include <cuda_runtime.h>
#include <cstdint>

#define NPROP   2048
#define MAXN    256
#define D1      64
#define D2      128
#define D3      256
#define MIN_PTS 4
#define EPS     1e-6f

// ---- smem layout (float offsets) ----
#define OFF_FE   0                          // 256 pooled feats
#define H1TROW   264                        // 256 + 8 pad (conflict-free col writes / B-frag reads)
#define H2TROW   264
#define OFF_H1T  256                        // h1 transposed [i=64][pt]   (16896 floats)
#define OFF_H2T  (OFF_H1T + D1 * H1TROW)    // h2 transposed [j=128][pt]  (33792 floats)
#define SMEM_FLOATS (OFF_H2T + D2 * H2TROW) // 50944
#define SMEM_BYTES  (SMEM_FLOATS * 4)       // 203,776 B

// round fp32 -> nearest tf32-representable value (bits / float)
__device__ __forceinline__ uint32_t f32_to_tf32_bits(float x) {
    uint32_t r;
    asm("cvt.rna.tf32.f32 %0, %1;" : "=r"(r) : "f"(x));
    return r;
}
__device__ __forceinline__ float f32_to_tf32_f(float x) {
    return __uint_as_float(f32_to_tf32_bits(x));
}

// D(16x8) += A(16x8,row) * B(8x8,col), tf32 in, f32 accum (sm_80+ baseline PTX).
#define MMA_TF32(c, a, b) \
    asm volatile("mma.sync.aligned.m16n8k8.row.col.f32.tf32.tf32.f32 " \
        "{%0,%1,%2,%3}, {%4,%5,%6,%7}, {%8,%9}, {%0,%1,%2,%3};" \
        : "+f"((c)[0]), "+f"((c)[1]), "+f"((c)[2]), "+f"((c)[3]) \
        : "r"((a)[0]), "r"((a)[1]), "r"((a)[2]), "r"((a)[3]), \
          "r"((b)[0]), "r"((b)[1]))

__global__ __launch_bounds__(256, 1)
void refine_head_kernel(const float* __restrict__ points,
                        const int*   __restrict__ counts,
                        const float* __restrict__ proposals,
                        const float* __restrict__ W1, const float* __restrict__ b1,
                        const float* __restrict__ W2, const float* __restrict__ b2,
                        const float* __restrict__ W3, const float* __restrict__ b3,
                        const float* __restrict__ Wc, const float* __restrict__ bc,
                        const float* __restrict__ Wr, const float* __restrict__ br,
                        float* __restrict__ out)
{
    extern __shared__ float sm[];
    const int b    = blockIdx.x;
    const int tid  = threadIdx.x;
    const int wid  = tid >> 5;
    const int lane = tid & 31;
    const int tid4 = lane & 3;
    const int gid  = lane >> 2;
    const int n    = counts[b];

    // Invalid proposal: outputs are pure biases (uniform early-out).
    if (n < MIN_PTS) {
        if (tid == 0) out[b] = bc[0];
        if (tid < 6)  out[NPROP + b * 6 + tid] = br[tid];
        return;
    }

    // ---- Phase 0: thread = point (only the first n unique points matter —
    // the reference's arange(256)%n gather merely duplicates points and
    // max-pool is duplicate-invariant). Layer 1 scalar -> h1t[i][pt], tf32. ----
    if (tid < n) {
        const float* pp = points + ((long)b * MAXN + tid) * 3;
        const float* pr = proposals + b * 6;
        const float c0 = (pp[0] - pr[0]) / (fabsf(pr[3]) + EPS);
        const float c1 = (pp[1] - pr[1]) / (fabsf(pr[4]) + EPS);
        const float c2 = (pp[2] - pr[2]) / (fabsf(pr[5]) + EPS);

        #pragma unroll
        for (int q = 0; q < 16; q++) {
            float4 a  = __ldg((const float4*)(W1)       + q);
            float4 d  = __ldg((const float4*)(W1 + 64)  + q);
            float4 e  = __ldg((const float4*)(W1 + 128) + q);
            float4 f  = __ldg((const float4*)(b1)       + q);
            float h0 = fmaxf(fmaf(c0, a.x, fmaf(c1, d.x, fmaf(c2, e.x, f.x))), 0.f);
            float h1v= fmaxf(fmaf(c0, a.y, fmaf(c1, d.y, fmaf(c2, e.y, f.y))), 0.f);
            float h2v= fmaxf(fmaf(c0, a.z, fmaf(c1, d.z, fmaf(c2, e.z, f.z))), 0.f);
            float h3 = fmaxf(fmaf(c0, a.w, fmaf(c1, d.w, fmaf(c2, e.w, f.w))), 0.f);
            sm[OFF_H1T + (q*4+0) * H1TROW + tid] = f32_to_tf32_f(h0);
            sm[OFF_H1T + (q*4+1) * H1TROW + tid] = f32_to_tf32_f(h1v);
            sm[OFF_H1T + (q*4+2) * H1TROW + tid] = f32_to_tf32_f(h2v);
            sm[OFF_H1T + (q*4+3) * H1TROW + tid] = f32_to_tf32_f(h3);
        }
    }
    __syncthreads();

    const int nchunks = (n + 15) >> 4;

    // ---- Layer 2 on tensor cores: D[ch][pt] = W2T @ h1t. Warp w owns the
    // m16 channel tile [w*16, w*16+16). Output IS the h2t layout layer 3 reads. ----
    {
        const int chb = wid * 16;

        uint32_t A2[8][4];
        #pragma unroll
        for (int s = 0; s < 8; s++) {
            const int j0 = s * 8 + tid4;   // k index (layer-1 channel i)
            A2[s][0] = f32_to_tf32_bits(__ldg(W2 + j0 * D2 + chb + gid));
            A2[s][1] = f32_to_tf32_bits(__ldg(W2 + j0 * D2 + chb + gid + 8));
            A2[s][2] = f32_to_tf32_bits(__ldg(W2 + (j0 + 4) * D2 + chb + gid));
            A2[s][3] = f32_to_tf32_bits(__ldg(W2 + (j0 + 4) * D2 + chb + gid + 8));
        }
        const float b2v0 = __ldg(b2 + chb + gid);
        const float b2v1 = __ldg(b2 + chb + gid + 8);

        for (int ck = 0; ck < nchunks; ck++) {
            const int colb = ck * 16;
            float c2[2][4];
            #pragma unroll
            for (int nt = 0; nt < 2; nt++)
                #pragma unroll
                for (int q = 0; q < 4; q++) c2[nt][q] = 0.f;

            #pragma unroll
            for (int s = 0; s < 8; s++) {
                uint32_t bf[2][2];
                #pragma unroll
                for (int nt = 0; nt < 2; nt++) {
                    const int col = colb + nt * 8 + gid;
                    bf[nt][0] = __float_as_uint(
                        sm[OFF_H1T + (s * 8 + tid4) * H1TROW + col]);
                    bf[nt][1] = __float_as_uint(
                        sm[OFF_H1T + (s * 8 + tid4 + 4) * H1TROW + col]);
                }
                MMA_TF32(c2[0], A2[s], bf[0]);
                MMA_TF32(c2[1], A2[s], bf[1]);
            }

            // epilogue: relu + bias, tf32-round, store into h2t
            #pragma unroll
            for (int nt = 0; nt < 2; nt++) {
                const int col0 = colb + nt * 8 + 2 * tid4;
                float2 v0, v1;
                v0.x = f32_to_tf32_f(fmaxf(c2[nt][0] + b2v0, 0.f));
                v0.y = f32_to_tf32_f(fmaxf(c2[nt][1] + b2v0, 0.f));
                v1.x = f32_to_tf32_f(fmaxf(c2[nt][2] + b2v1, 0.f));
                v1.y = f32_to_tf32_f(fmaxf(c2[nt][3] + b2v1, 0.f));
                *(float2*)&sm[OFF_H2T + (chb + gid)     * H2TROW + col0] = v0;
                *(float2*)&sm[OFF_H2T + (chb + gid + 8) * H2TROW + col0] = v1;
            }
        }
    }
    __syncthreads();

    // ---- Layer 3 + max-pool on tensor cores. Warp w owns channels
    // [w*32, w*32+32): 2 m16 tiles. A = W3T in regs (L2-hot); B = h2t. ----
    {
        const int chb = wid * 32;

        uint32_t A[16][2][4];
        #pragma unroll
        for (int s = 0; s < 16; s++) {
            const int j0 = s * 8 + tid4;
            #pragma unroll
            for (int mt = 0; mt < 2; mt++) {
                const int ch = chb + mt * 16 + gid;
                A[s][mt][0] = f32_to_tf32_bits(__ldg(W3 + j0 * D3 + ch));
                A[s][mt][1] = f32_to_tf32_bits(__ldg(W3 + j0 * D3 + ch + 8));
                A[s][mt][2] = f32_to_tf32_bits(__ldg(W3 + (j0 + 4) * D3 + ch));
                A[s][mt][3] = f32_to_tf32_bits(__ldg(W3 + (j0 + 4) * D3 + ch + 8));
            }
        }

        float mx[4] = {-3.402823466e38f, -3.402823466e38f,
                       -3.402823466e38f, -3.402823466e38f};   // [mt*2 + rowhalf]

        for (int ck = 0; ck < nchunks; ck++) {
            const int colb = ck * 16;
            float c[2][2][4];
            #pragma unroll
            for (int mt = 0; mt < 2; mt++)
                #pragma unroll
                for (int nt = 0; nt < 2; nt++)
                    #pragma unroll
                    for (int q = 0; q < 4; q++) c[mt][nt][q] = 0.f;

            #pragma unroll
            for (int s = 0; s < 16; s++) {
                uint32_t bf[2][2];
                #pragma unroll
                for (int nt = 0; nt < 2; nt++) {
                    const int col = colb + nt * 8 + gid;
                    bf[nt][0] = __float_as_uint(
                        sm[OFF_H2T + (s * 8 + tid4) * H2TROW + col]);
                    bf[nt][1] = __float_as_uint(
                        sm[OFF_H2T + (s * 8 + tid4 + 4) * H2TROW + col]);
                }
                #pragma unroll
                for (int mt = 0; mt < 2; mt++)
                    #pragma unroll
                    for (int nt = 0; nt < 2; nt++)
                        MMA_TF32(c[mt][nt], A[s][mt], bf[nt]);
            }

            // fold D into running per-row max (mask cols >= n)
            #pragma unroll
            for (int mt = 0; mt < 2; mt++) {
                #pragma unroll
                for (int nt = 0; nt < 2; nt++) {
                    const int col0 = colb + nt * 8 + 2 * tid4;
                    if (col0 < n) {
                        mx[mt*2+0] = fmaxf(mx[mt*2+0], c[mt][nt][0]);
                        mx[mt*2+1] = fmaxf(mx[mt*2+1], c[mt][nt][2]);
                    }
                    if (col0 + 1 < n) {
                        mx[mt*2+0] = fmaxf(mx[mt*2+0], c[mt][nt][1]);
                        mx[mt*2+1] = fmaxf(mx[mt*2+1], c[mt][nt][3]);
                    }
                }
            }
        }

        // cross-lane max over the 4 lanes of each quad
        #pragma unroll
        for (int o = 1; o < 4; o <<= 1) {
            #pragma unroll
            for (int q = 0; q < 4; q++)
                mx[q] = fmaxf(mx[q], __shfl_xor_sync(0xffffffffu, mx[q], o));
        }
        if (tid4 == 0) {
            #pragma unroll
            for (int mt = 0; mt < 2; mt++)
                #pragma unroll
                for (int rh = 0; rh < 2; rh++) {
                    const int ch = chb + mt * 16 + rh * 8 + gid;
                    sm[OFF_FE + ch] = mx[mt*2+rh] + __ldg(b3 + ch);
                }
        }
    }
    __syncthreads();

    // ---- Heads: 7 warps, each one dot(feats, column) + bias ----
    {
        if (wid < 7) {
            float s = 0.f;
            if (wid == 0) {
                #pragma unroll
                for (int k = lane; k < D3; k += 32) s += sm[OFF_FE + k] * __ldg(Wc + k);
            } else {
                const int r = wid - 1;
                #pragma unroll
                for (int k = lane; k < D3; k += 32) s += sm[OFF_FE + k] * __ldg(Wr + k * 6 + r);
            }
            #pragma unroll
            for (int off = 16; off > 0; off >>= 1)
                s += __shfl_down_sync(0xffffffffu, s, off);
            if (lane == 0) {
                if (wid == 0) out[b] = s + bc[0];
                else          out[NPROP + b * 6 + (wid - 1)] = s + br[wid - 1];
            }
        }
    }
}

extern "C" void kernel_launch(void* const* d_in, const int* in_sizes, int n_in,
                              void* d_out, int out_size)
{
    const float* points    = (const float*)d_in[0];
    const int*   counts    = (const int*)  d_in[1];
    const float* proposals = (const float*)d_in[2];
    const float* W1 = (const float*)d_in[3];
    const float* b1 = (const float*)d_in[4];
    const float* W2 = (const float*)d_in[5];
    const float* b2 = (const float*)d_in[6];
    const float* W3 = (const float*)d_in[7];
    const float* b3 = (const float*)d_in[8];
    const float* Wc = (const float*)d_in[9];
    const float* bc = (const float*)d_in[10];
    const float* Wr = (const float*)d_in[11];
    const float* br = (const float*)d_in[12];
    float* out = (float*)d_out;

    cudaFuncSetAttribute(refine_head_kernel,
                         cudaFuncAttributeMaxDynamicSharedMemorySize, SMEM_BYTES);
    refine_head_kernel<<<NPROP, 256, SMEM_BYTES>>>(
        points, counts, proposals, W1, b1, W2, b2, W3, b3, Wc, bc, Wr, br, out);
}